// round 5
// baseline (speedup 1.0000x reference)
#include <cuda_runtime.h>
#include <cstdint>

// ===========================================================================
// AxisAttention via mma.sync tf32, k-permuted float2-fragment layout.
// 3xTF32 split precision (512-thread CTAs) for q/k projections and QK^T;
// single-pass tf32 (256-thread, occ 2) for v-proj, PV, out-proj.
// B=4, N=2048, D=DA=512.
// ===========================================================================

constexpr int BB  = 4;
constexpr int SEQ = 2048;
constexpr int DIM = 512;
constexpr float SCALE_F = 22.62741699796952f;  // sqrt(512), multiplied

constexpr size_t BND = (size_t)BB * SEQ * DIM;

// ---------------- device global scratch (no runtime allocation) -----------
__device__ float g_in_hi[2 * BND];     // [query ; key_value] split-hi
__device__ float g_in_lo[2 * BND];
__device__ float g_qk_hi[2 * BND];     // [q ; k] projections split-hi
__device__ float g_qk_lo[2 * BND];
__device__ float g_vt[(size_t)BB * DIM * SEQ];   // V^T per batch [DIM, SEQ]
__device__ float g_s[(size_t)BB * SEQ * SEQ];    // scores / probs
__device__ float g_o[BND];
__device__ float g_wqk_hi[2 * DIM * DIM];        // [Wq^T ; Wk^T]
__device__ float g_wqk_lo[2 * DIM * DIM];
__device__ float g_wvt[DIM * DIM];
__device__ float g_wot[DIM * DIM];

// ---------------- helpers ---------------------------------------------------
__device__ __forceinline__ uint32_t smem_u32(const void* p) {
    uint32_t a;
    asm("{ .reg .u64 t; cvta.to.shared.u64 t, %1; cvt.u32.u64 %0, t; }"
        : "=r"(a) : "l"(p));
    return a;
}
__device__ __forceinline__ float tf32_rna(float x) {
    uint32_t u;
    asm("cvt.rna.tf32.f32 %0, %1;" : "=r"(u) : "f"(x));
    return __uint_as_float(u);
}
__device__ __forceinline__ void cp16(uint32_t saddr, const void* g) {
    asm volatile("cp.async.cg.shared.global [%0], [%1], 16;"
                 :: "r"(saddr), "l"(g) : "memory");
}
__device__ __forceinline__ void cp_commit() {
    asm volatile("cp.async.commit_group;" ::: "memory");
}
template <int N>
__device__ __forceinline__ void cp_wait() {
    asm volatile("cp.async.wait_group %0;" :: "n"(N) : "memory");
}

// k-permutation within each 16-block: (t, t+4) -> (2t, 2t+1) in each half.
__device__ __forceinline__ int perm16(int t) {
    const int lo = t & 7;
    return (t & 8) + 2 * (lo & 3) + (lo >> 2);
}
__device__ __forceinline__ int permk(int k) {
    return (k & ~15) | perm16(k & 15);
}

// mma.sync m16n8k8 tf32
__device__ __forceinline__ void mma8(float* c, float a0, float a1, float a2,
                                     float a3, float b0, float b1) {
    asm volatile(
        "mma.sync.aligned.m16n8k8.row.col.f32.tf32.tf32.f32 "
        "{%0,%1,%2,%3}, {%4,%5,%6,%7}, {%8,%9}, {%0,%1,%2,%3};"
        : "+f"(c[0]), "+f"(c[1]), "+f"(c[2]), "+f"(c[3])
        : "r"(__float_as_uint(a0)), "r"(__float_as_uint(a1)),
          "r"(__float_as_uint(a2)), "r"(__float_as_uint(a3)),
          "r"(__float_as_uint(b0)), "r"(__float_as_uint(b1)));
}

// ---------------- tiles: 128 rows x 32 k-floats, row stride 40 floats ------
constexpr int LDW    = 40;
constexpr int TILE_F = 128 * LDW;     // 5120 floats
constexpr int TILE_B = TILE_F * 4;    // 20480 bytes

template <int THREADS>
__device__ __forceinline__ void load_tile32(
    uint32_t sbase, const float* __restrict__ g, int ld, int tid)
{
#pragma unroll
    for (int i = 0; i < 1024 / THREADS; i++) {
        const int f  = tid + i * THREADS;  // 0..1023 float4s
        const int r  = f >> 3;
        const int c4 = (f & 7) << 2;
        cp16(sbase + (uint32_t)(r * LDW + c4) * 4, g + (size_t)r * ld + c4);
    }
}

// ---------------- main GEMM -------------------------------------------------
// D[m,n] = alpha * sum_k A[m,k]*B[n,k] (+bias[n]) (+resid), 128x128 CTA tile,
// K-chunk 32. PASSES==3: 512 threads, 4x4 warps, warp tile 32x32.
// PASSES==1: 256 threads (occ 2), 2x4 warps, warp tile 64x32.
// EPI: 0=split hi/lo+bias (perm cols; z selects bias/bias2),
// 1=transposed VT+bias (perm seq), 2=alpha scale (perm cols),
// 3=plain tf32 (perm cols), 4=bias+residual.
template <int PASSES, int EPI>
__global__ void __launch_bounds__((PASSES == 3) ? 512 : 256,
                                  (PASSES == 3) ? 1 : 2) gemm_mma(
    const float* __restrict__ Ahi, const float* __restrict__ Alo,
    const float* __restrict__ Bhi, const float* __restrict__ Blo,
    float* __restrict__ C, float* __restrict__ C2,
    const float* __restrict__ bias, const float* __restrict__ bias2,
    const float* __restrict__ resid,
    int K, int lda, int ldb, int ldc,
    size_t sA, size_t sB, size_t sC, float alpha)
{
    constexpr int NT      = (PASSES == 3) ? 4 : 2;   // tiles per stage
    constexpr int THREADS = (PASSES == 3) ? 512 : 256;
    constexpr int IT      = (PASSES == 3) ? 2 : 4;   // m-subtiles per warp
    extern __shared__ float smf[];
    const uint32_t sb = smem_u32(smf);

    const int tid    = threadIdx.x;
    const int lane   = tid & 31;
    const int wid    = tid >> 5;
    const int warp_m = wid >> 2;
    const int warp_n = wid & 3;
    const int n0 = blockIdx.x * 128;
    const int m0 = blockIdx.y * 128;
    const int z  = blockIdx.z;

    const float* bias_z = (EPI == 0 && z == 1) ? bias2 : bias;

    const float* A0 = Ahi + (size_t)z * sA + (size_t)m0 * lda;
    const float* B0 = Bhi + (size_t)z * sB + (size_t)n0 * ldb;
    const float* A1 = (PASSES == 3) ? Alo + (size_t)z * sA + (size_t)m0 * lda : nullptr;
    const float* B1 = (PASSES == 3) ? Blo + (size_t)z * sB + (size_t)n0 * ldb : nullptr;

    float acc[IT][4][4];
#pragma unroll
    for (int i = 0; i < IT; i++)
#pragma unroll
        for (int j = 0; j < 4; j++)
#pragma unroll
            for (int l = 0; l < 4; l++) acc[i][j][l] = 0.0f;

    const int nch = K / 32;

    auto load_stage = [&](int buf, int c) {
        const uint32_t st = sb + (uint32_t)buf * NT * TILE_B;
        load_tile32<THREADS>(st,          A0 + c * 32, lda, tid);
        load_tile32<THREADS>(st + TILE_B, B0 + c * 32, ldb, tid);
        if (PASSES == 3) {
            load_tile32<THREADS>(st + 2 * TILE_B, A1 + c * 32, lda, tid);
            load_tile32<THREADS>(st + 3 * TILE_B, B1 + c * 32, ldb, tid);
        }
    };

    load_stage(0, 0);
    cp_commit();

    const int arow0 = warp_m * (IT * 16) + (lane >> 2);
    const int bcol0 = warp_n * 32 + (lane >> 2);
    const int kq2   = 2 * (lane & 3);

    for (int c = 0; c < nch; c++) {
        if (c + 1 < nch) {
            load_stage((c + 1) & 1, c + 1);
            cp_commit();
            cp_wait<1>();
        } else {
            cp_wait<0>();
        }
        __syncthreads();

        const float* st  = smf + (size_t)(c & 1) * NT * TILE_F;
        const float* Ath = st;
        const float* Bth = st + TILE_F;
        const float* Atl = st + 2 * TILE_F;
        const float* Btl = st + 3 * TILE_F;

#pragma unroll
        for (int s = 0; s < 4; s++) {
            const int ko = s * 8 + kq2;
            float2 a0[IT], a1[IT], b0[4];
#pragma unroll
            for (int i = 0; i < IT; i++) {
                a0[i] = *reinterpret_cast<const float2*>(
                    Ath + (size_t)(arow0 + i * 16) * LDW + ko);
                a1[i] = *reinterpret_cast<const float2*>(
                    Ath + (size_t)(arow0 + i * 16 + 8) * LDW + ko);
            }
#pragma unroll
            for (int j = 0; j < 4; j++)
                b0[j] = *reinterpret_cast<const float2*>(
                    Bth + (size_t)(bcol0 + j * 8) * LDW + ko);
#pragma unroll
            for (int i = 0; i < IT; i++)
#pragma unroll
                for (int j = 0; j < 4; j++)
                    mma8(acc[i][j], a0[i].x, a1[i].x, a0[i].y, a1[i].y,
                         b0[j].x, b0[j].y);

            if (PASSES == 3) {
                float2 bl[4];
#pragma unroll
                for (int j = 0; j < 4; j++)
                    bl[j] = *reinterpret_cast<const float2*>(
                        Btl + (size_t)(bcol0 + j * 8) * LDW + ko);
#pragma unroll
                for (int i = 0; i < IT; i++)
#pragma unroll
                    for (int j = 0; j < 4; j++)
                        mma8(acc[i][j], a0[i].x, a1[i].x, a0[i].y, a1[i].y,
                             bl[j].x, bl[j].y);
                float2 al0[IT], al1[IT];
#pragma unroll
                for (int i = 0; i < IT; i++) {
                    al0[i] = *reinterpret_cast<const float2*>(
                        Atl + (size_t)(arow0 + i * 16) * LDW + ko);
                    al1[i] = *reinterpret_cast<const float2*>(
                        Atl + (size_t)(arow0 + i * 16 + 8) * LDW + ko);
                }
#pragma unroll
                for (int i = 0; i < IT; i++)
#pragma unroll
                    for (int j = 0; j < 4; j++)
                        mma8(acc[i][j], al0[i].x, al1[i].x, al0[i].y, al1[i].y,
                             b0[j].x, b0[j].y);
            }
        }
        __syncthreads();
    }

    // ---------------- epilogue ----------------
    float* Cz = C + (size_t)z * sC;
#pragma unroll
    for (int i = 0; i < IT; i++) {
#pragma unroll
        for (int j = 0; j < 4; j++) {
            const float* a4 = acc[i][j];
            const int r0 = m0 + warp_m * (IT * 16) + i * 16 + (lane >> 2);
            const int c0 = n0 + warp_n * 32 + j * 8 + 2 * (lane & 3);
            if (EPI == 0) {            // split hi/lo + bias, perm cols
                float* C2z = C2 + (size_t)z * sC;
                const float bx = bias_z[c0], by = bias_z[c0 + 1];
                const int p0 = permk(c0), p1 = permk(c0 + 1);
                const float v0 = a4[0] + bx, v1 = a4[1] + by;
                const float v2 = a4[2] + bx, v3 = a4[3] + by;
                float h;
                h = tf32_rna(v0); Cz[(size_t)r0 * ldc + p0] = h;
                C2z[(size_t)r0 * ldc + p0] = tf32_rna(v0 - h);
                h = tf32_rna(v1); Cz[(size_t)r0 * ldc + p1] = h;
                C2z[(size_t)r0 * ldc + p1] = tf32_rna(v1 - h);
                h = tf32_rna(v2); Cz[(size_t)(r0 + 8) * ldc + p0] = h;
                C2z[(size_t)(r0 + 8) * ldc + p0] = tf32_rna(v2 - h);
                h = tf32_rna(v3); Cz[(size_t)(r0 + 8) * ldc + p1] = h;
                C2z[(size_t)(r0 + 8) * ldc + p1] = tf32_rna(v3 - h);
            } else if (EPI == 1) {     // transposed VT[b][dim][seq], perm seq
                const float bx = bias[c0], by = bias[c0 + 1];
                const int b0i = r0 >> 11,        sx0 = permk(r0 & (SEQ - 1));
                const int b1i = (r0 + 8) >> 11,  sx1 = permk((r0 + 8) & (SEQ - 1));
                float* p0 = C + (size_t)b0i * DIM * SEQ;
                float* p1 = C + (size_t)b1i * DIM * SEQ;
                p0[(size_t)c0 * SEQ + sx0]       = tf32_rna(a4[0] + bx);
                p0[(size_t)(c0 + 1) * SEQ + sx0] = tf32_rna(a4[1] + by);
                p1[(size_t)c0 * SEQ + sx1]       = tf32_rna(a4[2] + bx);
                p1[(size_t)(c0 + 1) * SEQ + sx1] = tf32_rna(a4[3] + by);
            } else if (EPI == 2) {     // alpha scale (scores), perm cols
                const int p0 = permk(c0), p1 = permk(c0 + 1);
                Cz[(size_t)r0 * ldc + p0]       = alpha * a4[0];
                Cz[(size_t)r0 * ldc + p1]       = alpha * a4[1];
                Cz[(size_t)(r0 + 8) * ldc + p0] = alpha * a4[2];
                Cz[(size_t)(r0 + 8) * ldc + p1] = alpha * a4[3];
            } else if (EPI == 3) {     // plain tf32-rounded (O), perm cols
                const int p0 = permk(c0), p1 = permk(c0 + 1);
                Cz[(size_t)r0 * ldc + p0]       = tf32_rna(a4[0]);
                Cz[(size_t)r0 * ldc + p1]       = tf32_rna(a4[1]);
                Cz[(size_t)(r0 + 8) * ldc + p0] = tf32_rna(a4[2]);
                Cz[(size_t)(r0 + 8) * ldc + p1] = tf32_rna(a4[3]);
            } else {                   // bias + residual (final out), no perm
                const float bx = bias[c0], by = bias[c0 + 1];
                const float2 rs0 = *reinterpret_cast<const float2*>(
                    &resid[(size_t)r0 * ldc + c0]);
                const float2 rs1 = *reinterpret_cast<const float2*>(
                    &resid[(size_t)(r0 + 8) * ldc + c0]);
                float2 v0, v1;
                v0.x = a4[0] + bx + rs0.x; v0.y = a4[1] + by + rs0.y;
                v1.x = a4[2] + bx + rs1.x; v1.y = a4[3] + by + rs1.y;
                *reinterpret_cast<float2*>(&Cz[(size_t)r0 * ldc + c0]) = v0;
                *reinterpret_cast<float2*>(&Cz[(size_t)(r0 + 8) * ldc + c0]) = v1;
            }
        }
    }
}

// ---------------- prep: fused splits into combined buffer, perm k ----------
__global__ void split_two(const float4* __restrict__ q, const float4* __restrict__ kv,
                          float* __restrict__ dh, float* __restrict__ dl, int n4)
{
    const int id = blockIdx.x * 256 + threadIdx.x;
    if (id >= 2 * n4) return;
    const float4 v = (id < n4) ? q[id] : kv[id - n4];
    const int e0 = id * 4;
    const int base = e0 & ~511;        // row start (DIM=512 divides rows)
    float vv[4] = {v.x, v.y, v.z, v.w};
#pragma unroll
    for (int u = 0; u < 4; u++) {
        const int k = (e0 + u) & 511;
        const int pk = permk(k);
        const float h = tf32_rna(vv[u]);
        dh[base + pk] = h;
        dl[base + pk] = tf32_rna(vv[u] - h);
    }
}

// ---------------- prep: fused weight transposes, perm k --------------------
__global__ void wprep_all(const float* __restrict__ Wq, const float* __restrict__ Wk,
                          const float* __restrict__ Wv, const float* __restrict__ Wo,
                          float* __restrict__ wqk_hi, float* __restrict__ wqk_lo,
                          float* __restrict__ vh, float* __restrict__ oh)
{
    const int idx = blockIdx.x * 256 + threadIdx.x;  // 0 .. 512*512-1
    const int wsel = blockIdx.y;                     // 0..3
    const int n = idx & 511;        // coalesced read over n
    const int k = idx >> 9;
    const float* W; float *Th, *Tl;
    if      (wsel == 0) { W = Wq; Th = wqk_hi;             Tl = wqk_lo; }
    else if (wsel == 1) { W = Wk; Th = wqk_hi + DIM * DIM; Tl = wqk_lo + DIM * DIM; }
    else if (wsel == 2) { W = Wv; Th = vh; Tl = nullptr; }
    else                { W = Wo; Th = oh; Tl = nullptr; }
    const float w = W[(size_t)k * DIM + n];
    const float h = tf32_rna(w);
    const size_t dst = (size_t)n * DIM + permk(k);
    Th[dst] = h;
    if (Tl) Tl[dst] = tf32_rna(w - h);
}

// ---------------- softmax (rows of 2048), output tf32-rounded --------------
__global__ void __launch_bounds__(256) softmax_rows(float* __restrict__ S)
{
    const size_t row = blockIdx.x;
    float* p = S + row * (size_t)SEQ;
    const int t = threadIdx.x;
    float vals[8];
    float m = -3.402823466e38f;
#pragma unroll
    for (int i = 0; i < 8; i++) { vals[i] = p[t + i * 256]; m = fmaxf(m, vals[i]); }
    __shared__ float red[256];
    red[t] = m; __syncthreads();
#pragma unroll
    for (int s = 128; s > 0; s >>= 1) { if (t < s) red[t] = fmaxf(red[t], red[t+s]); __syncthreads(); }
    m = red[0]; __syncthreads();
    float sum = 0.0f;
#pragma unroll
    for (int i = 0; i < 8; i++) { vals[i] = __expf(vals[i] - m); sum += vals[i]; }
    red[t] = sum; __syncthreads();
#pragma unroll
    for (int s = 128; s > 0; s >>= 1) { if (t < s) red[t] += red[t+s]; __syncthreads(); }
    const float inv = 1.0f / red[0];
#pragma unroll
    for (int i = 0; i < 8; i++) p[t + i * 256] = tf32_rna(vals[i] * inv);
}

// ---------------- launcher --------------------------------------------------
extern "C" void kernel_launch(void* const* d_in, const int* in_sizes, int n_in,
                              void* d_out, int out_size)
{
    (void)in_sizes; (void)n_in; (void)out_size;
    const float* query     = (const float*)d_in[0];
    const float* key_value = (const float*)d_in[1];
    const float* Wq = (const float*)d_in[2];
    const float* bq = (const float*)d_in[3];
    const float* Wk = (const float*)d_in[4];
    const float* bk = (const float*)d_in[5];
    const float* Wv = (const float*)d_in[6];
    const float* bv = (const float*)d_in[7];
    const float* Wo = (const float*)d_in[8];
    const float* bo = (const float*)d_in[9];
    float* out = (float*)d_out;

    float *in_hi, *in_lo, *qk_hi, *qk_lo, *vt, *s, *o;
    float *wqk_hi, *wqk_lo, *wvt, *wot;
    cudaGetSymbolAddress((void**)&in_hi,  g_in_hi);
    cudaGetSymbolAddress((void**)&in_lo,  g_in_lo);
    cudaGetSymbolAddress((void**)&qk_hi,  g_qk_hi);
    cudaGetSymbolAddress((void**)&qk_lo,  g_qk_lo);
    cudaGetSymbolAddress((void**)&vt,     g_vt);
    cudaGetSymbolAddress((void**)&s,      g_s);
    cudaGetSymbolAddress((void**)&o,      g_o);
    cudaGetSymbolAddress((void**)&wqk_hi, g_wqk_hi);
    cudaGetSymbolAddress((void**)&wqk_lo, g_wqk_lo);
    cudaGetSymbolAddress((void**)&wvt,    g_wvt);
    cudaGetSymbolAddress((void**)&wot,    g_wot);

    constexpr int SM3 = 2 * 4 * TILE_B;   // 163840 B
    constexpr int SM1 = 2 * 2 * TILE_B;   // 81920 B
    cudaFuncSetAttribute(gemm_mma<3,0>, cudaFuncAttributeMaxDynamicSharedMemorySize, SM3);
    cudaFuncSetAttribute(gemm_mma<3,2>, cudaFuncAttributeMaxDynamicSharedMemorySize, SM3);
    cudaFuncSetAttribute(gemm_mma<1,1>, cudaFuncAttributeMaxDynamicSharedMemorySize, SM1);
    cudaFuncSetAttribute(gemm_mma<1,3>, cudaFuncAttributeMaxDynamicSharedMemorySize, SM1);
    cudaFuncSetAttribute(gemm_mma<1,4>, cudaFuncAttributeMaxDynamicSharedMemorySize, SM1);

    const size_t sQKV = (size_t)SEQ * DIM;
    const size_t sS   = (size_t)SEQ * SEQ;
    const size_t sVT  = (size_t)DIM * SEQ;
    const int n4 = (int)(BND / 4);
    const float* q_hi = qk_hi;
    const float* q_lo = qk_lo;
    const float* k_hi = qk_hi + BND;
    const float* k_lo = qk_lo + BND;

    // 0: fused input splits (query + key_value)
    split_two<<<(2 * n4 + 255) / 256, 256>>>((const float4*)query,
        (const float4*)key_value, in_hi, in_lo, n4);
    // 1: fused weight transposes
    {
        dim3 g((DIM * DIM) / 256, 4);
        wprep_all<<<g, 256>>>(Wq, Wk, Wv, Wo, wqk_hi, wqk_lo, wvt, wot);
    }

    // 2: G1+G2 fused: q,k projections (3xTF32, 512 thr, z = projection)
    {
        dim3 grid(DIM / 128, (BB * SEQ) / 128, 2);
        gemm_mma<3,0><<<grid, 512, SM3>>>(in_hi, in_lo, wqk_hi, wqk_lo,
            qk_hi, qk_lo, bq, bk, nullptr, DIM, DIM, DIM, DIM,
            BND, (size_t)DIM * DIM, BND, 1.0f);
    }

    // 3: G4: S = sqrt(512) * q @ k^T (3xTF32, 512 thr, batched)
    {
        dim3 grid(SEQ / 128, SEQ / 128, BB);
        gemm_mma<3,2><<<grid, 512, SM3>>>(q_hi, q_lo, k_hi, k_lo,
            s, nullptr, nullptr, nullptr, nullptr, DIM, DIM, DIM, SEQ,
            sQKV, sQKV, sS, SCALE_F);
    }

    // 4: G3: v projection -> transposed VT (1x)
    {
        dim3 grid(DIM / 128, (BB * SEQ) / 128, 1);
        gemm_mma<1,1><<<grid, 256, SM1>>>(in_hi + BND, nullptr, wvt, nullptr,
            vt, nullptr, bv, nullptr, nullptr, DIM, DIM, DIM, 0, 0, 0, 0, 1.0f);
    }

    // 5: softmax
    softmax_rows<<<BB * SEQ, 256>>>(s);

    // 6: G5: O = P @ V (1x, batched), B = VT
    {
        dim3 grid(DIM / 128, SEQ / 128, BB);
        gemm_mma<1,3><<<grid, 256, SM1>>>(s, nullptr, vt, nullptr,
            o, nullptr, nullptr, nullptr, nullptr, SEQ, SEQ, SEQ, DIM,
            sS, sVT, sQKV, 1.0f);
    }

    // 7: G6: out = query + O @ Wo + bo (1x)
    {
        dim3 grid(DIM / 128, (BB * SEQ) / 128, 1);
        gemm_mma<1,4><<<grid, 256, SM1>>>(o, nullptr, wot, nullptr,
            out, nullptr, bo, nullptr, query, DIM, DIM, DIM, DIM, 0, 0, 0, 1.0f);
    }
}